// round 9
// baseline (speedup 1.0000x reference)
#include <cuda_runtime.h>
#include <cuda_bf16.h>
#include <cstdint>

// ROIAlign, OUT=15x15, SCALE=1/16, SR=2
// x: [2,256,64,64] f32; boxes: [512,4] f32; batch_idx: [512] i32
// out: [512,256,15,15] f32
//
// v5: like v4 (separable y-combine -> smem vrow -> x-combine) but with
// 32-channel chunks: vrow = 23KB -> 8 blocks/SM (64 warps, 100% occ) to
// saturate the L1 data path that v4's ncu shows as the binding pipe.

#define HH 64
#define WW 64
#define CC 256
#define OUT_HW 15
#define NBOX 512
#define PW 12
#define NCH 8                            // float4 per position = 32 channels
#define NCHUNK (CC / (NCH * 4))          // 8 chunks

#define VROW_F4  (OUT_HW * PW * NCH)     // 1440 float4 = 23040 B
#define SMEM_DYN (VROW_F4 * 16)

// vrow index with XOR swizzle: pos in [0,180), c4 in [0,8)
#define VIDX(pos, c4) (((pos) * NCH) + ((c4) ^ ((pos) & 7)))

// channels-last scratch: [2,64,64,256] f32 = 8MB
__device__ float g_xt[2 * HH * WW * CC];

// ---------------------------------------------------------------------------
// Transpose [B,C,H*W] -> [B,H*W,C] via 32x32 smem tiles
// ---------------------------------------------------------------------------
__global__ __launch_bounds__(256) void transpose_kernel(const float* __restrict__ x) {
    __shared__ float tile[32][33];
    int b   = blockIdx.z;
    int hw0 = blockIdx.x * 32;
    int c0  = blockIdx.y * 32;
    const float* src = x + ((size_t)b * CC) * (HH * WW);
    #pragma unroll
    for (int i = threadIdx.y; i < 32; i += 8)
        tile[i][threadIdx.x] = src[(size_t)(c0 + i) * (HH * WW) + hw0 + threadIdx.x];
    __syncthreads();
    float* dst = g_xt + (size_t)b * (HH * WW) * CC;
    #pragma unroll
    for (int i = threadIdx.y; i < 32; i += 8)
        dst[(size_t)(hw0 + i) * CC + c0 + threadIdx.x] = tile[threadIdx.x][i];
}

// ---------------------------------------------------------------------------
// Axis corner-list builder: dedup the <=4 bilinear corners of the 2
// subsamples into <=3 (clamped absolute index, weight) pairs. v = validity*0.5.
// ---------------------------------------------------------------------------
__device__ __forceinline__ void axis_bin(float a1, float bin, int bin_i,
                                         int size, int* o_idx, float* o_wt, int* o_n) {
    int   idx[3];
    float wt[3];
    int   cnt = 0;
    #pragma unroll
    for (int s = 0; s < 2; s++) {
        float p = a1 + ((float)(bin_i * 2 + s) + 0.5f) * 0.5f * bin;
        const float v = (p >= -1.0f && p <= (float)size) ? 0.5f : 0.0f;
        p = fminf(fmaxf(p, 0.0f), (float)(size - 1));
        int lo = (int)floorf(p);
        if (lo > size - 1) lo = size - 1;
        const int   hi = min(lo + 1, size - 1);
        const float f  = p - (float)lo;
        int   ci[2] = { lo, hi };
        float cw[2] = { (1.0f - f) * v, f * v };
        #pragma unroll
        for (int k = 0; k < 2; k++) {
            int m;
            for (m = 0; m < cnt; m++)
                if (idx[m] == ci[k]) { wt[m] += cw[k]; break; }
            if (m == cnt && cnt < 3) { idx[cnt] = ci[k]; wt[cnt] = cw[k]; cnt++; }
        }
    }
    *o_n = cnt;
    for (int m = 0; m < cnt; m++) { o_idx[m] = idx[m]; o_wt[m] = wt[m]; }
}

// ---------------------------------------------------------------------------
// ROI kernel: grid (8 chunk, 512 box), 256 threads.
// ---------------------------------------------------------------------------
__global__ __launch_bounds__(256) void roi_kernel(const float* __restrict__ boxes,
                                                  const int* __restrict__ batch_idx,
                                                  float* __restrict__ out) {
    extern __shared__ float4 vrow[];     // swizzled [pos 0..179][c4 0..7]

    __shared__ int    s_xn[OUT_HW];
    __shared__ int    s_xc[OUT_HW][3];   // relative x (0..11)
    __shared__ float  s_xw[OUT_HW][3];
    __shared__ int    s_yn[OUT_HW];
    __shared__ int    s_yoff[OUT_HW][3]; // absolute row offset into g_xt (floats)
    __shared__ float  s_yw[OUT_HW][3];

    const int chunk = blockIdx.x;
    const int n     = blockIdx.y;
    const int tid   = threadIdx.x;

    // ---- box geometry (broadcast loads) ----
    const float bx1 = boxes[n * 4 + 0] * 0.0625f;
    const float by1 = boxes[n * 4 + 1] * 0.0625f;
    const float bx2 = boxes[n * 4 + 2] * 0.0625f;
    const float by2 = boxes[n * 4 + 3] * 0.0625f;
    const float bin_w = fmaxf(bx2 - bx1, 1.0f) * (1.0f / OUT_HW);
    const float bin_h = fmaxf(by2 - by1, 1.0f) * (1.0f / OUT_HW);
    const int   b     = batch_idx[n];

    float p0x = fminf(fmaxf(bx1 + 0.25f * bin_w, 0.0f), (float)(WW - 1));
    const int x_base = (int)floorf(p0x);

    // ---- per-bin axis corner lists ----
    if (tid < OUT_HW) {
        int idx[3]; float wt[3]; int cnt;
        axis_bin(bx1, bin_w, tid, WW, idx, wt, &cnt);
        s_xn[tid] = cnt;
        for (int m = 0; m < cnt; m++) { s_xc[tid][m] = idx[m] - x_base; s_xw[tid][m] = wt[m]; }
    } else if (tid >= 32 && tid < 32 + OUT_HW) {
        const int h = tid - 32;
        int idx[3]; float wt[3]; int cnt;
        axis_bin(by1, bin_h, h, HH, idx, wt, &cnt);
        s_yn[h] = cnt;
        for (int m = 0; m < cnt; m++) {
            s_yoff[h][m] = (b * (HH * WW) + idx[m] * WW) * CC;
            s_yw[h][m]   = wt[m];
        }
    }
    __syncthreads();

    // ---- stage 1: y-combine directly from g_xt into vrow ----
    // 8 consecutive lanes read one 128B row segment (32 channels).
    {
        const float* srcc = g_xt + chunk * (NCH * 4);
        #pragma unroll
        for (int i = tid; i < VROW_F4; i += 256) {
            const int c4  = i & (NCH - 1);
            const int pos = i / NCH;         // h*12 + x, 0..179
            const int h   = pos / PW;
            const int x   = pos - h * PW;
            const int xabs = min(x_base + x, WW - 1);
            const int coff = xabs * CC + c4 * 4;
            const int ny   = s_yn[h];
            float4 acc = {0.f, 0.f, 0.f, 0.f};
            #pragma unroll
            for (int yi = 0; yi < 3; yi++) {
                if (yi < ny) {
                    const float  wy = s_yw[h][yi];
                    const float4 v  = *reinterpret_cast<const float4*>(srcc + s_yoff[h][yi] + coff);
                    acc.x = fmaf(wy, v.x, acc.x);
                    acc.y = fmaf(wy, v.y, acc.y);
                    acc.z = fmaf(wy, v.z, acc.z);
                    acc.w = fmaf(wy, v.w, acc.w);
                }
            }
            vrow[VIDX(pos, c4)] = acc;
        }
    }
    __syncthreads();

    if (tid >= OUT_HW * OUT_HW) return;

    // ---- stage 2: x-combine, thread = bin (coalesced output stores) ----
    const int h = tid / OUT_HW;
    const int w = tid - h * OUT_HW;

    const int nx = s_xn[w];
    int   pbase[3];
    int   psw[3];
    float wxs[3];
    #pragma unroll
    for (int xi = 0; xi < 3; xi++) {
        const int pos = h * PW + (xi < nx ? s_xc[w][xi] : 0);
        pbase[xi] = pos * NCH;
        psw[xi]   = pos & 7;
        wxs[xi]   = xi < nx ? s_xw[w][xi] : 0.0f;
    }

    float* obase = out + ((size_t)n * CC + chunk * (NCH * 4)) * (OUT_HW * OUT_HW) + tid;

    #pragma unroll
    for (int cg = 0; cg < 2; cg++) {
        float4 a0 = {0.f, 0.f, 0.f, 0.f};
        float4 a1 = {0.f, 0.f, 0.f, 0.f};
        float4 a2 = {0.f, 0.f, 0.f, 0.f};
        float4 a3 = {0.f, 0.f, 0.f, 0.f};
        #pragma unroll
        for (int xi = 0; xi < 3; xi++) {
            if (xi < nx) {
                const float g  = wxs[xi];
                const int   bb = pbase[xi];
                const int   sw = psw[xi];
                float4 v;
                v = vrow[bb + ((cg * 4 + 0) ^ sw)];
                a0.x = fmaf(g, v.x, a0.x); a0.y = fmaf(g, v.y, a0.y);
                a0.z = fmaf(g, v.z, a0.z); a0.w = fmaf(g, v.w, a0.w);
                v = vrow[bb + ((cg * 4 + 1) ^ sw)];
                a1.x = fmaf(g, v.x, a1.x); a1.y = fmaf(g, v.y, a1.y);
                a1.z = fmaf(g, v.z, a1.z); a1.w = fmaf(g, v.w, a1.w);
                v = vrow[bb + ((cg * 4 + 2) ^ sw)];
                a2.x = fmaf(g, v.x, a2.x); a2.y = fmaf(g, v.y, a2.y);
                a2.z = fmaf(g, v.z, a2.z); a2.w = fmaf(g, v.w, a2.w);
                v = vrow[bb + ((cg * 4 + 3) ^ sw)];
                a3.x = fmaf(g, v.x, a3.x); a3.y = fmaf(g, v.y, a3.y);
                a3.z = fmaf(g, v.z, a3.z); a3.w = fmaf(g, v.w, a3.w);
            }
        }
        float* o = obase + (size_t)(cg * 16) * (OUT_HW * OUT_HW);
        const int S = OUT_HW * OUT_HW;
        o[0 * S]  = a0.x; o[1 * S]  = a0.y; o[2 * S]  = a0.z; o[3 * S]  = a0.w;
        o[4 * S]  = a1.x; o[5 * S]  = a1.y; o[6 * S]  = a1.z; o[7 * S]  = a1.w;
        o[8 * S]  = a2.x; o[9 * S]  = a2.y; o[10 * S] = a2.z; o[11 * S] = a2.w;
        o[12 * S] = a3.x; o[13 * S] = a3.y; o[14 * S] = a3.z; o[15 * S] = a3.w;
    }
}

// ---------------------------------------------------------------------------
extern "C" void kernel_launch(void* const* d_in, const int* in_sizes, int n_in,
                              void* d_out, int out_size) {
    const float* x     = (const float*)d_in[0];
    const float* boxes = (const float*)d_in[1];
    const int*   bidx  = (const int*)d_in[2];
    float*       out   = (float*)d_out;

    (void)in_sizes; (void)n_in; (void)out_size;

    cudaFuncSetAttribute(roi_kernel, cudaFuncAttributeMaxDynamicSharedMemorySize, SMEM_DYN);

    dim3 tb(32, 8);
    dim3 tg((HH * WW) / 32, CC / 32, 2);
    transpose_kernel<<<tg, tb>>>(x);

    dim3 rg(NCHUNK, NBOX);
    roi_kernel<<<rg, 256, SMEM_DYN>>>(boxes, bidx, out);
}